// round 4
// baseline (speedup 1.0000x reference)
#include <cuda_runtime.h>
#include <math.h>
#include <stdint.h>

#define NB 32
#define NC 256
#define NH 64
#define NW 64
#define NHW 4096
#define NCHW (NC*NHW)
#define EPSV 1e-5f

// Scratch (allocation-free rule: __device__ globals)
__device__ float g_pooled[NB*NC];
__device__ int   g_idx[NB];
__device__ float g_feat[(size_t)NB*NCHW];   // fp32 feature scratch

// ---------------------------------------------------------------------------
// 1) Global average pool per (b,c)
// ---------------------------------------------------------------------------
__global__ void pool_kernel(const float* __restrict__ x) {
    int bc = blockIdx.x;
    const float4* p = reinterpret_cast<const float4*>(x + (size_t)bc * NHW);
    float s = 0.f;
    for (int i = threadIdx.x; i < NHW/4; i += 256) {
        float4 v = p[i];
        s += (v.x + v.y) + (v.z + v.w);
    }
    __shared__ float red[8];
    #pragma unroll
    for (int o = 16; o > 0; o >>= 1) s += __shfl_down_sync(0xffffffffu, s, o);
    if ((threadIdx.x & 31) == 0) red[threadIdx.x >> 5] = s;
    __syncthreads();
    if (threadIdx.x < 8) {
        float t = red[threadIdx.x];
        #pragma unroll
        for (int o = 4; o > 0; o >>= 1) t += __shfl_down_sync(0xffu, t, o);
        if (threadIdx.x == 0) g_pooled[bc] = t * (1.0f / NHW);
    }
}

// ---------------------------------------------------------------------------
// 2) Router: argmax of logits (softmax monotone; top-1 weight == 1 exactly)
// ---------------------------------------------------------------------------
__global__ void route_kernel(const float* __restrict__ rw, const float* __restrict__ rb) {
    int b = threadIdx.x;
    if (b >= NB) return;
    float best = -1e30f; int bi = 0;
    #pragma unroll
    for (int j = 0; j < 3; j++) {
        float s = rb[j];
        const float* w = rw + j*NC;
        const float* p = g_pooled + b*NC;
        for (int c = 0; c < NC; c++) s = fmaf(p[c], w[c], s);
        if (s > best) { best = s; bi = j; }
    }
    g_idx[b] = bi;
}

// ---------------------------------------------------------------------------
// 3a) Depthwise 3x3 conv (dil D) + BN + exact GELU — smem-tiled plane kernel.
//     One block per (b,c) plane; zero-padded 68x70 smem tile -> no bounds
//     checks; each thread computes 16 contiguous pixels of one row-quarter.
// ---------------------------------------------------------------------------
#define SMC 70   // smem row stride (words): conflict-free for compute pattern

template<int D>
__device__ __forceinline__ void dwconv_plane(
    float (*sm)[SMC], const float* __restrict__ xp, const float* __restrict__ kw9,
    float scale, float mm, float bb, float* __restrict__ outp)
{
    const int tid = threadIdx.x;

    // zero-fill whole tile (border becomes zero padding)
    float* smf = &sm[0][0];
    for (int i = tid; i < 68*SMC; i += 256) smf[i] = 0.f;
    __syncthreads();

    // load 64x64 interior: 1024 float4s, 4 per thread
    #pragma unroll
    for (int i = 0; i < 4; i++) {
        int idx = tid + i*256;
        int y = idx >> 4, x4 = (idx & 15) * 4;
        float4 v = reinterpret_cast<const float4*>(xp)[idx];
        sm[y+2][x4+2+0] = v.x;
        sm[y+2][x4+2+1] = v.y;
        sm[y+2][x4+2+2] = v.z;
        sm[y+2][x4+2+3] = v.w;
    }
    __syncthreads();

    const int y  = tid >> 2;
    const int x0 = (tid & 3) * 16;

    float acc[16];
    #pragma unroll
    for (int j = 0; j < 16; j++) acc[j] = 0.f;

    #pragma unroll
    for (int dy = 0; dy < 3; dy++) {
        const float* row = &sm[y + 2 + (dy-1)*D][x0 + 2 - D];
        const float w0 = kw9[dy*3 + 0];
        const float w1 = kw9[dy*3 + 1];
        const float w2 = kw9[dy*3 + 2];
        float v[16 + 2*D];
        #pragma unroll
        for (int j = 0; j < 16 + 2*D; j++) v[j] = row[j];
        #pragma unroll
        for (int j = 0; j < 16; j++)
            acc[j] = fmaf(w0, v[j], fmaf(w1, v[j+D], fmaf(w2, v[j+2*D], acc[j])));
    }

    float* op = outp + y*NW + x0;
    #pragma unroll
    for (int q = 0; q < 4; q++) {
        float4 o;
        float* oe = &o.x;
        #pragma unroll
        for (int j = 0; j < 4; j++) {
            float z = (acc[q*4 + j] - mm) * scale + bb;
            oe[j] = z * normcdff(z);          // exact GELU
        }
        reinterpret_cast<float4*>(op)[q] = o;
    }
}

__global__ void __launch_bounds__(256) dwconv_bn_gelu_kernel(
    const float* __restrict__ x,
    const float* __restrict__ k0, const float* __restrict__ g0, const float* __restrict__ b0,
    const float* __restrict__ m0, const float* __restrict__ v0,
    const float* __restrict__ k1, const float* __restrict__ g1, const float* __restrict__ b1,
    const float* __restrict__ m1, const float* __restrict__ v1)
{
    __shared__ float sm[68][SMC];
    const int b = blockIdx.y;
    const int e = g_idx[b];
    if (e == 2) return;
    const int c = blockIdx.x;

    const float gg = (e == 0 ? g0[c] : g1[c]);
    const float vv = (e == 0 ? v0[c] : v1[c]);
    const float mm = (e == 0 ? m0[c] : m1[c]);
    const float bb = (e == 0 ? b0[c] : b1[c]);
    const float scale = gg * rsqrtf(vv + EPSV);
    const float* kw = (e == 0 ? k0 : k1) + c * 9;
    const float* xp = x + ((size_t)b*NC + c) * NHW;
    float* outp = g_feat + ((size_t)b*NC + c) * NHW;

    if (e == 0) dwconv_plane<1>(sm, xp, kw, scale, mm, bb, outp);
    else        dwconv_plane<2>(sm, xp, kw, scale, mm, bb, outp);
}

// ---------------------------------------------------------------------------
// TF32 tensor-core GEMM tile (proven R2 version): C(128x128)=A(128x256)*B(256x128)
// A row-major ld=256, B row-major ld=4096, C row-major ld=4096.
// 256 threads, 8 warps; warp tile 32x64 via m16n8k8 tf32 mma.
// ---------------------------------------------------------------------------
__device__ __forceinline__ uint32_t f2tf32(float f) {
    uint32_t r;
    asm("cvt.rna.tf32.f32 %0, %1;" : "=r"(r) : "f"(f));
    return r;
}

__device__ __forceinline__ void mma_tf32(float c[4], const uint32_t a[4], const uint32_t b[2]) {
    asm volatile(
        "mma.sync.aligned.m16n8k8.row.col.f32.tf32.tf32.f32 "
        "{%0,%1,%2,%3}, {%4,%5,%6,%7}, {%8,%9}, {%0,%1,%2,%3};"
        : "+f"(c[0]), "+f"(c[1]), "+f"(c[2]), "+f"(c[3])
        : "r"(a[0]), "r"(a[1]), "r"(a[2]), "r"(a[3]),
          "r"(b[0]), "r"(b[1]));
}

#define SPAD 136   // row stride: 136 % 32 == 8 -> frag loads conflict-free

template<bool BN_GELU>
__device__ __forceinline__ void mma_gemm_tile(
    const float* __restrict__ A, const float* __restrict__ Bm, float* __restrict__ Cm,
    const float* __restrict__ p0, const float* __restrict__ p1,
    const float* __restrict__ p2, const float* __restrict__ p3)
{
    __shared__ uint32_t As[2][16][SPAD];
    __shared__ uint32_t Bs[2][16][SPAD];

    const int tid  = threadIdx.x;
    const int lane = tid & 31;
    const int wid  = tid >> 5;
    const int wm   = wid & 3;
    const int wn   = wid >> 2;
    const int gID  = lane >> 2;
    const int qid  = lane & 3;
    const int m0   = blockIdx.y * 128;
    const int n0   = blockIdx.x * 128;

    const int am  = tid >> 2;
    const int aq  = tid & 3;
    const int bk  = tid >> 5;
    const int bn4 = (tid & 31) * 4;

    float acc[2][8][4];
    #pragma unroll
    for (int i = 0; i < 2; i++)
        #pragma unroll
        for (int j = 0; j < 8; j++)
            #pragma unroll
            for (int t = 0; t < 4; t++) acc[i][j][t] = 0.f;

    {
        float4 a0 = *reinterpret_cast<const float4*>(A + (size_t)(m0 + am)      * NC + aq*4);
        float4 a1 = *reinterpret_cast<const float4*>(A + (size_t)(m0 + am + 64) * NC + aq*4);
        float4 b0 = *reinterpret_cast<const float4*>(Bm + (size_t)(bk)     * NHW + n0 + bn4);
        float4 b1 = *reinterpret_cast<const float4*>(Bm + (size_t)(bk + 8) * NHW + n0 + bn4);
        #pragma unroll
        for (int j = 0; j < 4; j++) {
            As[0][aq*4 + j][am]      = f2tf32((&a0.x)[j]);
            As[0][aq*4 + j][am + 64] = f2tf32((&a1.x)[j]);
        }
        uint32_t* bp0 = &Bs[0][bk][bn4];
        uint32_t* bp1 = &Bs[0][bk + 8][bn4];
        bp0[0]=f2tf32(b0.x); bp0[1]=f2tf32(b0.y); bp0[2]=f2tf32(b0.z); bp0[3]=f2tf32(b0.w);
        bp1[0]=f2tf32(b1.x); bp1[1]=f2tf32(b1.y); bp1[2]=f2tf32(b1.z); bp1[3]=f2tf32(b1.w);
    }
    __syncthreads();

    int buf = 0;
    for (int k0 = 0; k0 < NC; k0 += 16) {
        const bool has_next = (k0 + 16) < NC;
        float4 a0n, a1n, b0n, b1n;
        if (has_next) {
            int kn = k0 + 16;
            a0n = *reinterpret_cast<const float4*>(A + (size_t)(m0 + am)      * NC + kn + aq*4);
            a1n = *reinterpret_cast<const float4*>(A + (size_t)(m0 + am + 64) * NC + kn + aq*4);
            b0n = *reinterpret_cast<const float4*>(Bm + (size_t)(kn + bk)     * NHW + n0 + bn4);
            b1n = *reinterpret_cast<const float4*>(Bm + (size_t)(kn + bk + 8) * NHW + n0 + bn4);
        }

        #pragma unroll
        for (int ks = 0; ks < 2; ks++) {
            const int kb = ks * 8;
            uint32_t af[2][4], bf[8][2];
            #pragma unroll
            for (int mt = 0; mt < 2; mt++) {
                const int mb = wm*32 + mt*16;
                af[mt][0] = As[buf][kb + qid]    [mb + gID];
                af[mt][1] = As[buf][kb + qid]    [mb + gID + 8];
                af[mt][2] = As[buf][kb + 4 + qid][mb + gID];
                af[mt][3] = As[buf][kb + 4 + qid][mb + gID + 8];
            }
            #pragma unroll
            for (int nt = 0; nt < 8; nt++) {
                const int nb = wn*64 + nt*8;
                bf[nt][0] = Bs[buf][kb + qid]    [nb + gID];
                bf[nt][1] = Bs[buf][kb + 4 + qid][nb + gID];
            }
            #pragma unroll
            for (int mt = 0; mt < 2; mt++)
                #pragma unroll
                for (int nt = 0; nt < 8; nt++)
                    mma_tf32(acc[mt][nt], af[mt], bf[nt]);
        }

        if (has_next) {
            const int nb_ = buf ^ 1;
            #pragma unroll
            for (int j = 0; j < 4; j++) {
                As[nb_][aq*4 + j][am]      = f2tf32((&a0n.x)[j]);
                As[nb_][aq*4 + j][am + 64] = f2tf32((&a1n.x)[j]);
            }
            uint32_t* bp0 = &Bs[nb_][bk][bn4];
            uint32_t* bp1 = &Bs[nb_][bk + 8][bn4];
            bp0[0]=f2tf32(b0n.x); bp0[1]=f2tf32(b0n.y); bp0[2]=f2tf32(b0n.z); bp0[3]=f2tf32(b0n.w);
            bp1[0]=f2tf32(b1n.x); bp1[1]=f2tf32(b1n.y); bp1[2]=f2tf32(b1n.z); bp1[3]=f2tf32(b1n.w);
            __syncthreads();
            buf = nb_;
        }
    }

    #pragma unroll
    for (int mt = 0; mt < 2; mt++) {
        #pragma unroll
        for (int half = 0; half < 2; half++) {
            const int o = m0 + wm*32 + mt*16 + half*8 + gID;
            float sc = 0.f, mm = 0.f, bb;
            if (BN_GELU) {
                sc = p0[o] * rsqrtf(p3[o] + EPSV);
                mm = p2[o];
                bb = p1[o];
            } else {
                bb = p0[o];
            }
            float* cp = Cm + (size_t)o * NHW + n0 + wn*64 + qid*2;
            #pragma unroll
            for (int nt = 0; nt < 8; nt++) {
                float z0 = acc[mt][nt][half*2 + 0];
                float z1 = acc[mt][nt][half*2 + 1];
                if (BN_GELU) {
                    z0 = (z0 - mm) * sc + bb; z0 = z0 * normcdff(z0);
                    z1 = (z1 - mm) * sc + bb; z1 = z1 * normcdff(z1);
                } else {
                    z0 += bb; z1 += bb;
                }
                *reinterpret_cast<float2*>(cp + nt*8) = make_float2(z0, z1);
            }
        }
    }
}

// 3b) Expert-2 feature stage: feat = bn_gelu(e2_k @ x[b]) — only for idx==2
__global__ void __launch_bounds__(256, 2) feat_gemm_kernel(
    const float* __restrict__ x, const float* __restrict__ e2k,
    const float* __restrict__ g, const float* __restrict__ bt,
    const float* __restrict__ m, const float* __restrict__ v)
{
    int b = blockIdx.z;
    if (g_idx[b] != 2) return;
    mma_gemm_tile<true>(e2k, x + (size_t)b*NCHW, g_feat + (size_t)b*NCHW, g, bt, m, v);
}

// 4) Final pointwise: out[b] = e{idx}_pw @ feat[b] + e{idx}_pb
__global__ void __launch_bounds__(256, 2) out_gemm_kernel(
    const float* __restrict__ w0, const float* __restrict__ pb0,
    const float* __restrict__ w1, const float* __restrict__ pb1,
    const float* __restrict__ w2, const float* __restrict__ pb2,
    float* __restrict__ out)
{
    int b = blockIdx.z;
    int e = g_idx[b];
    const float* A  = (e == 0) ? w0  : (e == 1 ? w1  : w2);
    const float* pb = (e == 0) ? pb0 : (e == 1 ? pb1 : pb2);
    mma_gemm_tile<false>(A, g_feat + (size_t)b*NCHW, out + (size_t)b*NCHW,
                         pb, nullptr, nullptr, nullptr);
}

// ---------------------------------------------------------------------------
extern "C" void kernel_launch(void* const* d_in, const int* in_sizes, int n_in,
                              void* d_out, int out_size) {
    const float* x    = (const float*)d_in[0];
    const float* rw   = (const float*)d_in[1];
    const float* rb   = (const float*)d_in[2];
    const float* e0_k = (const float*)d_in[3];
    const float* e0_g = (const float*)d_in[4];
    const float* e0_b = (const float*)d_in[5];
    const float* e0_m = (const float*)d_in[6];
    const float* e0_v = (const float*)d_in[7];
    const float* e0_pw= (const float*)d_in[8];
    const float* e0_pb= (const float*)d_in[9];
    const float* e1_k = (const float*)d_in[10];
    const float* e1_g = (const float*)d_in[11];
    const float* e1_b = (const float*)d_in[12];
    const float* e1_m = (const float*)d_in[13];
    const float* e1_v = (const float*)d_in[14];
    const float* e1_pw= (const float*)d_in[15];
    const float* e1_pb= (const float*)d_in[16];
    const float* e2_k = (const float*)d_in[17];
    const float* e2_g = (const float*)d_in[18];
    const float* e2_b = (const float*)d_in[19];
    const float* e2_m = (const float*)d_in[20];
    const float* e2_v = (const float*)d_in[21];
    const float* e2_pw= (const float*)d_in[22];
    const float* e2_pb= (const float*)d_in[23];
    float* out = (float*)d_out;

    pool_kernel<<<NB*NC, 256>>>(x);
    route_kernel<<<1, 32>>>(rw, rb);

    dwconv_bn_gelu_kernel<<<dim3(NC, NB), 256>>>(
        x, e0_k, e0_g, e0_b, e0_m, e0_v,
           e1_k, e1_g, e1_b, e1_m, e1_v);

    dim3 ggrid(NHW/128, NC/128, NB);   // (32, 2, 32)
    feat_gemm_kernel<<<ggrid, 256>>>(x, e2_k, e2_g, e2_b, e2_m, e2_v);
    out_gemm_kernel<<<ggrid, 256>>>(e0_pw, e0_pb, e1_pw, e1_pb, e2_pw, e2_pb, out);
}

// round 6
// speedup vs baseline: 1.2510x; 1.2510x over previous
#include <cuda_runtime.h>
#include <math.h>
#include <stdint.h>

#define NB 32
#define NC 256
#define NH 64
#define NW 64
#define NHW 4096
#define NCHW (NC*NHW)
#define EPSV 1e-5f

// Scratch (allocation-free rule: __device__ globals)
__device__ float g_pooled[NB*NC];
__device__ int   g_idx[NB];
__device__ float g_feat[(size_t)NB*NCHW];   // tf32-rounded feature scratch
__device__ float g_wt[4][NC*NC];            // tf32-rounded weights: e0_pw,e1_pw,e2_pw,e2_k

__device__ __forceinline__ uint32_t f2tf32(float f) {
    uint32_t r;
    asm("cvt.rna.tf32.f32 %0, %1;" : "=r"(r) : "f"(f));
    return r;
}
__device__ __forceinline__ float f2tf32f(float f) { return __uint_as_float(f2tf32(f)); }

// ---------------------------------------------------------------------------
// 1) Global average pool per (b,c)
// ---------------------------------------------------------------------------
__global__ void pool_kernel(const float* __restrict__ x) {
    int bc = blockIdx.x;
    const float4* p = reinterpret_cast<const float4*>(x + (size_t)bc * NHW);
    float s = 0.f;
    for (int i = threadIdx.x; i < NHW/4; i += 256) {
        float4 v = p[i];
        s += (v.x + v.y) + (v.z + v.w);
    }
    __shared__ float red[8];
    #pragma unroll
    for (int o = 16; o > 0; o >>= 1) s += __shfl_down_sync(0xffffffffu, s, o);
    if ((threadIdx.x & 31) == 0) red[threadIdx.x >> 5] = s;
    __syncthreads();
    if (threadIdx.x < 8) {
        float t = red[threadIdx.x];
        #pragma unroll
        for (int o = 4; o > 0; o >>= 1) t += __shfl_down_sync(0xffu, t, o);
        if (threadIdx.x == 0) g_pooled[bc] = t * (1.0f / NHW);
    }
}

// ---------------------------------------------------------------------------
// 2) Router: argmax of logits (softmax monotone; top-1 weight == 1 exactly)
// ---------------------------------------------------------------------------
__global__ void route_kernel(const float* __restrict__ rw, const float* __restrict__ rb) {
    int b = threadIdx.x;
    if (b >= NB) return;
    float best = -1e30f; int bi = 0;
    #pragma unroll
    for (int j = 0; j < 3; j++) {
        float s = rb[j];
        const float* w = rw + j*NC;
        const float* p = g_pooled + b*NC;
        for (int c = 0; c < NC; c++) s = fmaf(p[c], w[c], s);
        if (s > best) { best = s; bi = j; }
    }
    g_idx[b] = bi;
}

// ---------------------------------------------------------------------------
// 2b) Pre-convert weight matrices to tf32 (RNA) once
// ---------------------------------------------------------------------------
__global__ void prep_weights(const float* __restrict__ w0, const float* __restrict__ w1,
                             const float* __restrict__ w2, const float* __restrict__ k2) {
    int i = blockIdx.x * 256 + threadIdx.x;
    int m = i >> 16;
    int o = i & 0xFFFF;
    const float* src = (m == 0) ? w0 : (m == 1) ? w1 : (m == 2) ? w2 : k2;
    g_wt[m][o] = f2tf32f(src[o]);
}

// ---------------------------------------------------------------------------
// 3a) Depthwise 3x3 conv (dil D) + BN + exact GELU — smem-tiled plane kernel.
//     Output stored tf32-rounded (consumed by the GEMM).
// ---------------------------------------------------------------------------
#define SMC 70

template<int D>
__device__ __forceinline__ void dwconv_plane(
    float (*sm)[SMC], const float* __restrict__ xp, const float* __restrict__ kw9,
    float scale, float mm, float bb, float* __restrict__ outp)
{
    const int tid = threadIdx.x;
    float* smf = &sm[0][0];
    for (int i = tid; i < 68*SMC; i += 256) smf[i] = 0.f;
    __syncthreads();

    #pragma unroll
    for (int i = 0; i < 4; i++) {
        int idx = tid + i*256;
        int y = idx >> 4, x4 = (idx & 15) * 4;
        float4 v = reinterpret_cast<const float4*>(xp)[idx];
        sm[y+2][x4+2+0] = v.x;
        sm[y+2][x4+2+1] = v.y;
        sm[y+2][x4+2+2] = v.z;
        sm[y+2][x4+2+3] = v.w;
    }
    __syncthreads();

    const int y  = tid >> 2;
    const int x0 = (tid & 3) * 16;

    float acc[16];
    #pragma unroll
    for (int j = 0; j < 16; j++) acc[j] = 0.f;

    #pragma unroll
    for (int dy = 0; dy < 3; dy++) {
        const float* row = &sm[y + 2 + (dy-1)*D][x0 + 2 - D];
        const float w0 = kw9[dy*3 + 0];
        const float w1 = kw9[dy*3 + 1];
        const float w2 = kw9[dy*3 + 2];
        float v[16 + 2*D];
        #pragma unroll
        for (int j = 0; j < 16 + 2*D; j++) v[j] = row[j];
        #pragma unroll
        for (int j = 0; j < 16; j++)
            acc[j] = fmaf(w0, v[j], fmaf(w1, v[j+D], fmaf(w2, v[j+2*D], acc[j])));
    }

    float* op = outp + y*NW + x0;
    #pragma unroll
    for (int q = 0; q < 4; q++) {
        float4 o;
        float* oe = &o.x;
        #pragma unroll
        for (int j = 0; j < 4; j++) {
            float z = (acc[q*4 + j] - mm) * scale + bb;
            oe[j] = f2tf32f(z * normcdff(z));     // exact GELU, tf32-rounded
        }
        reinterpret_cast<float4*>(op)[q] = o;
    }
}

__global__ void __launch_bounds__(256) dwconv_bn_gelu_kernel(
    const float* __restrict__ x,
    const float* __restrict__ k0, const float* __restrict__ g0, const float* __restrict__ b0,
    const float* __restrict__ m0, const float* __restrict__ v0,
    const float* __restrict__ k1, const float* __restrict__ g1, const float* __restrict__ b1,
    const float* __restrict__ m1, const float* __restrict__ v1)
{
    __shared__ float sm[68][SMC];
    const int b = blockIdx.y;
    const int e = g_idx[b];
    if (e == 2) return;
    const int c = blockIdx.x;

    const float gg = (e == 0 ? g0[c] : g1[c]);
    const float vv = (e == 0 ? v0[c] : v1[c]);
    const float mm = (e == 0 ? m0[c] : m1[c]);
    const float bb = (e == 0 ? b0[c] : b1[c]);
    const float scale = gg * rsqrtf(vv + EPSV);
    const float* kw = (e == 0 ? k0 : k1) + c * 9;
    const float* xp = x + ((size_t)b*NC + c) * NHW;
    float* outp = g_feat + ((size_t)b*NC + c) * NHW;

    if (e == 0) dwconv_plane<1>(sm, xp, kw, scale, mm, bb, outp);
    else        dwconv_plane<2>(sm, xp, kw, scale, mm, bb, outp);
}

// ---------------------------------------------------------------------------
// TF32 mma.sync GEMM, LDS.128 fragment layouts.
// C(128x128) = A(128x256) * B(256x128); A,B pre-rounded tf32 (B optionally CVT).
// 8 warps, warp tile 32x64, m16n8k8, BK=16.
//
// A smem: [m][k''] dense 16 words/row (64B), k'' = (k&3)*4 + (k>>2),
//         chunk-XOR swizzle: chunk' = chunk ^ ((m ^ (m>>2)) & 3).
//         Compute: 1 LDS.128 per (mt,mh) covers BOTH k-steps. Conflict-free.
//         Staging: per-thread register transpose -> 4 STS.64. Conflict-free.
// B smem: [k][n'] rows of stride 136 words, n' = (n>>5)*32 + (n&7)*4 + ((n>>3)&3).
//         Compute: 1 LDS.128 per (kh,block32) covers 4 nt. Conflict-free.
//         Staging: 4 scattered STS.32 per float4 (~4-way, small volume).
// ---------------------------------------------------------------------------
__device__ __forceinline__ void mma_tf32(float c[4], const uint32_t a[4], const uint32_t b[2]) {
    asm volatile(
        "mma.sync.aligned.m16n8k8.row.col.f32.tf32.tf32.f32 "
        "{%0,%1,%2,%3}, {%4,%5,%6,%7}, {%8,%9}, {%0,%1,%2,%3};"
        : "+f"(c[0]), "+f"(c[1]), "+f"(c[2]), "+f"(c[3])
        : "r"(a[0]), "r"(a[1]), "r"(a[2]), "r"(a[3]),
          "r"(b[0]), "r"(b[1]));
}

#define SPB 136

template<bool BN_GELU, bool CVTB>
__device__ __forceinline__ void mma_gemm_tile(
    const float* __restrict__ A, const float* __restrict__ Bm, float* __restrict__ Cm,
    const float* __restrict__ p0, const float* __restrict__ p1,
    const float* __restrict__ p2, const float* __restrict__ p3)
{
    __shared__ __align__(16) uint32_t As[2][128*16];
    __shared__ __align__(16) uint32_t Bs[2][16][SPB];

    const int tid  = threadIdx.x;
    const int lane = tid & 31;
    const int wid  = tid >> 5;
    const int wm   = wid & 3;
    const int wn   = wid >> 2;
    const int gID  = lane >> 2;
    const int qid  = lane & 3;
    const int m0   = blockIdx.y * 128;
    const int n0   = blockIdx.x * 128;

    // A staging: one row per thread-pair
    const int am = tid >> 1;
    const int ah = tid & 1;
    const uint32_t hA = (uint32_t)((am ^ (am >> 2)) & 3);
    const float* aSrc = A + (size_t)(m0 + am) * NC + ah*8;

    // B staging: two chunks: id = tid, tid+256; k = id>>5, n-seg = (id&31)*4
    const int bk0 = tid >> 5;          // 0..7   (second: +8)
    const int bn  = (tid & 31) * 4;
    const float* bSrc = Bm + (size_t)bk0 * NHW + n0 + bn;

    // precompute B scatter columns for j=0..3 (same for both k-chunks)
    int bcol[4];
    #pragma unroll
    for (int j = 0; j < 4; j++) {
        int n = bn + j;
        bcol[j] = ((n >> 5) << 5) + ((n & 7) << 2) + ((n >> 3) & 3);
    }

    float acc[2][8][4];
    #pragma unroll
    for (int i = 0; i < 2; i++)
        #pragma unroll
        for (int j = 0; j < 8; j++)
            #pragma unroll
            for (int t = 0; t < 4; t++) acc[i][j][t] = 0.f;

    // ---- prologue: stage chunk kc=0 into buffer 0 ----
    {
        float4 fa0 = *reinterpret_cast<const float4*>(aSrc);
        float4 fa1 = *reinterpret_cast<const float4*>(aSrc + 4);
        float4 fb0 = *reinterpret_cast<const float4*>(bSrc);
        float4 fb1 = *reinterpret_cast<const float4*>(bSrc + (size_t)8 * NHW);
        #pragma unroll
        for (int j = 0; j < 4; j++) {
            uint32_t off = am*16 + ((j ^ hA) << 2) + ah*2;
            *reinterpret_cast<uint2*>(&As[0][off]) =
                make_uint2(__float_as_uint((&fa0.x)[j]), __float_as_uint((&fa1.x)[j]));
            uint32_t v0 = CVTB ? f2tf32((&fb0.x)[j]) : __float_as_uint((&fb0.x)[j]);
            uint32_t v1 = CVTB ? f2tf32((&fb1.x)[j]) : __float_as_uint((&fb1.x)[j]);
            Bs[0][bk0][bcol[j]]     = v0;
            Bs[0][bk0 + 8][bcol[j]] = v1;
        }
    }
    __syncthreads();

    int buf = 0;
    for (int kc = 0; kc < 16; kc++) {
        const bool has_next = (kc + 1) < 16;
        float4 fa0, fa1, fb0, fb1;
        if (has_next) {
            const int kn = (kc + 1) * 16;
            fa0 = *reinterpret_cast<const float4*>(aSrc + kn);
            fa1 = *reinterpret_cast<const float4*>(aSrc + kn + 4);
            fb0 = *reinterpret_cast<const float4*>(bSrc + (size_t)kn * NHW);
            fb1 = *reinterpret_cast<const float4*>(bSrc + (size_t)(kn + 8) * NHW);
        }

        // ---- compute on smem[buf] ----
        // A fragments: 4 LDS.128, each covers both k-steps
        uint4 aq[2][2];
        #pragma unroll
        for (int mt = 0; mt < 2; mt++)
            #pragma unroll
            for (int mh = 0; mh < 2; mh++) {
                int m = wm*32 + mt*16 + mh*8 + gID;
                uint32_t off = m*16 + (((qid ^ ((m ^ (m >> 2)) & 3))) << 2);
                aq[mt][mh] = *reinterpret_cast<const uint4*>(&As[buf][off]);
            }

        #pragma unroll
        for (int ks = 0; ks < 2; ks++) {
            // B fragments: 4 LDS.128 (kh x block32), each covers 4 nt
            uint4 bq[2][2];
            #pragma unroll
            for (int kh = 0; kh < 2; kh++)
                #pragma unroll
                for (int bl = 0; bl < 2; bl++) {
                    int krow = ks*8 + kh*4 + qid;
                    int ncol = (wn*2 + bl)*32 + gID*4;
                    bq[kh][bl] = *reinterpret_cast<const uint4*>(&Bs[buf][krow][ncol]);
                }

            #pragma unroll
            for (int mt = 0; mt < 2; mt++) {
                uint32_t a[4];
                if (ks == 0) {
                    a[0] = aq[mt][0].x; a[1] = aq[mt][1].x;
                    a[2] = aq[mt][0].y; a[3] = aq[mt][1].y;
                } else {
                    a[0] = aq[mt][0].z; a[1] = aq[mt][1].z;
                    a[2] = aq[mt][0].w; a[3] = aq[mt][1].w;
                }
                #pragma unroll
                for (int bl = 0; bl < 2; bl++) {
                    #pragma unroll
                    for (int c = 0; c < 4; c++) {
                        uint32_t b[2];
                        b[0] = (&bq[0][bl].x)[c];
                        b[1] = (&bq[1][bl].x)[c];
                        mma_tf32(acc[mt][bl*4 + c], a, b);
                    }
                }
            }
        }

        if (has_next) {
            const int nb_ = buf ^ 1;
            #pragma unroll
            for (int j = 0; j < 4; j++) {
                uint32_t off = am*16 + ((j ^ hA) << 2) + ah*2;
                *reinterpret_cast<uint2*>(&As[nb_][off]) =
                    make_uint2(__float_as_uint((&fa0.x)[j]), __float_as_uint((&fa1.x)[j]));
                uint32_t v0 = CVTB ? f2tf32((&fb0.x)[j]) : __float_as_uint((&fb0.x)[j]);
                uint32_t v1 = CVTB ? f2tf32((&fb1.x)[j]) : __float_as_uint((&fb1.x)[j]);
                Bs[nb_][bk0][bcol[j]]     = v0;
                Bs[nb_][bk0 + 8][bcol[j]] = v1;
            }
            __syncthreads();
            buf = nb_;
        }
    }

    // ---- epilogue (fragment layout unchanged from R2) ----
    #pragma unroll
    for (int mt = 0; mt < 2; mt++) {
        #pragma unroll
        for (int half = 0; half < 2; half++) {
            const int o = m0 + wm*32 + mt*16 + half*8 + gID;
            float sc = 0.f, mm = 0.f, bb;
            if (BN_GELU) {
                sc = p0[o] * rsqrtf(p3[o] + EPSV);
                mm = p2[o];
                bb = p1[o];
            } else {
                bb = p0[o];
            }
            float* cp = Cm + (size_t)o * NHW + n0 + wn*64 + qid*2;
            #pragma unroll
            for (int nt = 0; nt < 8; nt++) {
                float z0 = acc[mt][nt][half*2 + 0];
                float z1 = acc[mt][nt][half*2 + 1];
                if (BN_GELU) {
                    z0 = (z0 - mm) * sc + bb; z0 = f2tf32f(z0 * normcdff(z0));
                    z1 = (z1 - mm) * sc + bb; z1 = f2tf32f(z1 * normcdff(z1));
                } else {
                    z0 += bb; z1 += bb;
                }
                *reinterpret_cast<float2*>(cp + nt*8) = make_float2(z0, z1);
            }
        }
    }
}

// 3b) Expert-2 feature stage: feat = bn_gelu(e2_k @ x[b]) — only for idx==2
__global__ void __launch_bounds__(256, 2) feat_gemm_kernel(
    const float* __restrict__ x,
    const float* __restrict__ g, const float* __restrict__ bt,
    const float* __restrict__ m, const float* __restrict__ v)
{
    int b = blockIdx.z;
    if (g_idx[b] != 2) return;
    mma_gemm_tile<true, true>(g_wt[3], x + (size_t)b*NCHW, g_feat + (size_t)b*NCHW, g, bt, m, v);
}

// 4) Final pointwise: out[b] = e{idx}_pw @ feat[b] + e{idx}_pb
__global__ void __launch_bounds__(256, 2) out_gemm_kernel(
    const float* __restrict__ pb0, const float* __restrict__ pb1,
    const float* __restrict__ pb2, float* __restrict__ out)
{
    int b = blockIdx.z;
    int e = g_idx[b];
    const float* pb = (e == 0) ? pb0 : (e == 1 ? pb1 : pb2);
    mma_gemm_tile<false, false>(g_wt[e], g_feat + (size_t)b*NCHW, out + (size_t)b*NCHW,
                                pb, nullptr, nullptr, nullptr);
}

// ---------------------------------------------------------------------------
extern "C" void kernel_launch(void* const* d_in, const int* in_sizes, int n_in,
                              void* d_out, int out_size) {
    const float* x    = (const float*)d_in[0];
    const float* rw   = (const float*)d_in[1];
    const float* rb   = (const float*)d_in[2];
    const float* e0_k = (const float*)d_in[3];
    const float* e0_g = (const float*)d_in[4];
    const float* e0_b = (const float*)d_in[5];
    const float* e0_m = (const float*)d_in[6];
    const float* e0_v = (const float*)d_in[7];
    const float* e0_pw= (const float*)d_in[8];
    const float* e0_pb= (const float*)d_in[9];
    const float* e1_k = (const float*)d_in[10];
    const float* e1_g = (const float*)d_in[11];
    const float* e1_b = (const float*)d_in[12];
    const float* e1_m = (const float*)d_in[13];
    const float* e1_v = (const float*)d_in[14];
    const float* e1_pw= (const float*)d_in[15];
    const float* e1_pb= (const float*)d_in[16];
    const float* e2_k = (const float*)d_in[17];
    const float* e2_g = (const float*)d_in[18];
    const float* e2_b = (const float*)d_in[19];
    const float* e2_m = (const float*)d_in[20];
    const float* e2_v = (const float*)d_in[21];
    const float* e2_pw= (const float*)d_in[22];
    const float* e2_pb= (const float*)d_in[23];
    float* out = (float*)d_out;

    pool_kernel<<<NB*NC, 256>>>(x);
    prep_weights<<<1024, 256>>>(e0_pw, e1_pw, e2_pw, e2_k);
    route_kernel<<<1, 32>>>(rw, rb);

    dwconv_bn_gelu_kernel<<<dim3(NC, NB), 256>>>(
        x, e0_k, e0_g, e0_b, e0_m, e0_v,
           e1_k, e1_g, e1_b, e1_m, e1_v);

    dim3 ggrid(NHW/128, NC/128, NB);   // (32, 2, 32)
    feat_gemm_kernel<<<ggrid, 256>>>(x, e2_g, e2_b, e2_m, e2_v);
    out_gemm_kernel<<<ggrid, 256>>>(e0_pb, e1_pb, e2_pb, out);
}

// round 8
// speedup vs baseline: 1.3647x; 1.0909x over previous
#include <cuda_runtime.h>
#include <math.h>
#include <stdint.h>

#define NB 32
#define NC 256
#define NH 64
#define NW 64
#define NHW 4096
#define NCHW (NC*NHW)
#define EPSV 1e-5f

// Scratch (allocation-free rule: __device__ globals)
__device__ float g_pooled[NB*NC];
__device__ int   g_idx[NB];
__device__ float g_feat[(size_t)NB*NCHW];   // tf32-rounded feature scratch
__device__ float g_wt[4][NC*NC];            // tf32-rounded weights: e0_pw,e1_pw,e2_pw,e2_k

__device__ __forceinline__ uint32_t f2tf32(float f) {
    uint32_t r;
    asm("cvt.rna.tf32.f32 %0, %1;" : "=r"(r) : "f"(f));
    return r;
}
__device__ __forceinline__ float f2tf32f(float f) { return __uint_as_float(f2tf32(f)); }

// exact GELU: z * Phi(z) = 0.5 z (1 + erf(z/sqrt(2))). erff = short polynomial.
__device__ __forceinline__ float gelu_exact(float z) {
    return 0.5f * z * (1.0f + erff(z * 0.7071067811865475f));
}

// ---------------------------------------------------------------------------
// 1) Global average pool per (b,c)
// ---------------------------------------------------------------------------
__global__ void pool_kernel(const float* __restrict__ x) {
    int bc = blockIdx.x;
    const float4* p = reinterpret_cast<const float4*>(x + (size_t)bc * NHW);
    float s = 0.f;
    for (int i = threadIdx.x; i < NHW/4; i += 256) {
        float4 v = p[i];
        s += (v.x + v.y) + (v.z + v.w);
    }
    __shared__ float red[8];
    #pragma unroll
    for (int o = 16; o > 0; o >>= 1) s += __shfl_down_sync(0xffffffffu, s, o);
    if ((threadIdx.x & 31) == 0) red[threadIdx.x >> 5] = s;
    __syncthreads();
    if (threadIdx.x < 8) {
        float t = red[threadIdx.x];
        #pragma unroll
        for (int o = 4; o > 0; o >>= 1) t += __shfl_down_sync(0xffu, t, o);
        if (threadIdx.x == 0) g_pooled[bc] = t * (1.0f / NHW);
    }
}

// ---------------------------------------------------------------------------
// 2) Router: argmax of logits (softmax monotone; top-1 weight == 1 exactly)
// ---------------------------------------------------------------------------
__global__ void route_kernel(const float* __restrict__ rw, const float* __restrict__ rb) {
    int b = threadIdx.x;
    if (b >= NB) return;
    float best = -1e30f; int bi = 0;
    #pragma unroll
    for (int j = 0; j < 3; j++) {
        float s = rb[j];
        const float* w = rw + j*NC;
        const float* p = g_pooled + b*NC;
        for (int c = 0; c < NC; c++) s = fmaf(p[c], w[c], s);
        if (s > best) { best = s; bi = j; }
    }
    g_idx[b] = bi;
}

// ---------------------------------------------------------------------------
// 2b) Pre-convert weight matrices to tf32 (RNA) once
// ---------------------------------------------------------------------------
__global__ void prep_weights(const float* __restrict__ w0, const float* __restrict__ w1,
                             const float* __restrict__ w2, const float* __restrict__ k2) {
    int i = blockIdx.x * 256 + threadIdx.x;
    int m = i >> 16;
    int o = i & 0xFFFF;
    const float* src = (m == 0) ? w0 : (m == 1) ? w1 : (m == 2) ? w2 : k2;
    g_wt[m][o] = f2tf32f(src[o]);
}

// ---------------------------------------------------------------------------
// 3a) Depthwise 3x3 conv (dil D) + BN + exact GELU — smem-tiled plane kernel.
//     Border-only halo fill (interior overwritten by loads; disjoint -> 1 sync).
//     Output stored tf32-rounded (consumed by the GEMM).
// ---------------------------------------------------------------------------
#define SMC 70

template<int D>
__device__ __forceinline__ void dwconv_plane(
    float (*sm)[SMC], const float* __restrict__ xp, const float* __restrict__ kw9,
    float scale, float mm, float bb, float* __restrict__ outp)
{
    const int tid = threadIdx.x;

    // halo fill, part 1: rows {0,1,66,67} x cols 0..67 = 272 words (strided: 256 thr)
    for (int i = tid; i < 272; i += 256) {
        int r = i / 68, c = i % 68;
        sm[(r < 2) ? r : r + 64][c] = 0.f;
    }
    // halo fill, part 2: rows 2..65 x cols {0,1,66,67} = 256 words (1 per thread)
    {
        int r = 2 + (tid >> 2);
        int c = tid & 3;
        sm[r][(c < 2) ? c : c + 64] = 0.f;
    }

    // load 64x64 interior: 1024 float4s, 4 per thread
    #pragma unroll
    for (int i = 0; i < 4; i++) {
        int idx = tid + i*256;
        int y = idx >> 4, x4 = (idx & 15) * 4;
        float4 v = reinterpret_cast<const float4*>(xp)[idx];
        sm[y+2][x4+2+0] = v.x;
        sm[y+2][x4+2+1] = v.y;
        sm[y+2][x4+2+2] = v.z;
        sm[y+2][x4+2+3] = v.w;
    }
    __syncthreads();

    const int y  = tid >> 2;
    const int x0 = (tid & 3) * 16;

    float acc[16];
    #pragma unroll
    for (int j = 0; j < 16; j++) acc[j] = 0.f;

    #pragma unroll
    for (int dy = 0; dy < 3; dy++) {
        const float* row = &sm[y + 2 + (dy-1)*D][x0 + 2 - D];
        const float w0 = kw9[dy*3 + 0];
        const float w1 = kw9[dy*3 + 1];
        const float w2 = kw9[dy*3 + 2];
        float v[16 + 2*D];
        #pragma unroll
        for (int j = 0; j < 16 + 2*D; j++) v[j] = row[j];
        #pragma unroll
        for (int j = 0; j < 16; j++)
            acc[j] = fmaf(w0, v[j], fmaf(w1, v[j+D], fmaf(w2, v[j+2*D], acc[j])));
    }

    float* op = outp + y*NW + x0;
    #pragma unroll
    for (int q = 0; q < 4; q++) {
        float4 o;
        float* oe = &o.x;
        #pragma unroll
        for (int j = 0; j < 4; j++) {
            float z = (acc[q*4 + j] - mm) * scale + bb;
            oe[j] = f2tf32f(gelu_exact(z));   // exact GELU, tf32-rounded
        }
        reinterpret_cast<float4*>(op)[q] = o;
    }
}

__global__ void __launch_bounds__(256) dwconv_bn_gelu_kernel(
    const float* __restrict__ x,
    const float* __restrict__ k0, const float* __restrict__ g0, const float* __restrict__ b0,
    const float* __restrict__ m0, const float* __restrict__ v0,
    const float* __restrict__ k1, const float* __restrict__ g1, const float* __restrict__ b1,
    const float* __restrict__ m1, const float* __restrict__ v1)
{
    __shared__ float sm[68][SMC];
    const int b = blockIdx.y;
    const int e = g_idx[b];
    if (e == 2) return;
    const int c = blockIdx.x;

    const float gg = (e == 0 ? g0[c] : g1[c]);
    const float vv = (e == 0 ? v0[c] : v1[c]);
    const float mm = (e == 0 ? m0[c] : m1[c]);
    const float bb = (e == 0 ? b0[c] : b1[c]);
    const float scale = gg * rsqrtf(vv + EPSV);
    const float* kw = (e == 0 ? k0 : k1) + c * 9;
    const float* xp = x + ((size_t)b*NC + c) * NHW;
    float* outp = g_feat + ((size_t)b*NC + c) * NHW;

    if (e == 0) dwconv_plane<1>(sm, xp, kw, scale, mm, bb, outp);
    else        dwconv_plane<2>(sm, xp, kw, scale, mm, bb, outp);
}

// ---------------------------------------------------------------------------
// TF32 mma.sync GEMM, LDS.128 fragment layouts (proven R6 design).
// ---------------------------------------------------------------------------
__device__ __forceinline__ void mma_tf32(float c[4], const uint32_t a[4], const uint32_t b[2]) {
    asm volatile(
        "mma.sync.aligned.m16n8k8.row.col.f32.tf32.tf32.f32 "
        "{%0,%1,%2,%3}, {%4,%5,%6,%7}, {%8,%9}, {%0,%1,%2,%3};"
        : "+f"(c[0]), "+f"(c[1]), "+f"(c[2]), "+f"(c[3])
        : "r"(a[0]), "r"(a[1]), "r"(a[2]), "r"(a[3]),
          "r"(b[0]), "r"(b[1]));
}

#define SPB 136

template<bool BN_GELU, bool CVTB>
__device__ __forceinline__ void mma_gemm_tile(
    const float* __restrict__ A, const float* __restrict__ Bm, float* __restrict__ Cm,
    const float* __restrict__ p0, const float* __restrict__ p1,
    const float* __restrict__ p2, const float* __restrict__ p3)
{
    __shared__ __align__(16) uint32_t As[2][128*16];
    __shared__ __align__(16) uint32_t Bs[2][16][SPB];

    const int tid  = threadIdx.x;
    const int lane = tid & 31;
    const int wid  = tid >> 5;
    const int wm   = wid & 3;
    const int wn   = wid >> 2;
    const int gID  = lane >> 2;
    const int qid  = lane & 3;
    const int m0   = blockIdx.y * 128;
    const int n0   = blockIdx.x * 128;

    const int am = tid >> 1;
    const int ah = tid & 1;
    const uint32_t hA = (uint32_t)((am ^ (am >> 2)) & 3);
    const float* aSrc = A + (size_t)(m0 + am) * NC + ah*8;

    const int bk0 = tid >> 5;
    const int bn  = (tid & 31) * 4;
    const float* bSrc = Bm + (size_t)bk0 * NHW + n0 + bn;

    int bcol[4];
    #pragma unroll
    for (int j = 0; j < 4; j++) {
        int n = bn + j;
        bcol[j] = ((n >> 5) << 5) + ((n & 7) << 2) + ((n >> 3) & 3);
    }

    float acc[2][8][4];
    #pragma unroll
    for (int i = 0; i < 2; i++)
        #pragma unroll
        for (int j = 0; j < 8; j++)
            #pragma unroll
            for (int t = 0; t < 4; t++) acc[i][j][t] = 0.f;

    {
        float4 fa0 = *reinterpret_cast<const float4*>(aSrc);
        float4 fa1 = *reinterpret_cast<const float4*>(aSrc + 4);
        float4 fb0 = *reinterpret_cast<const float4*>(bSrc);
        float4 fb1 = *reinterpret_cast<const float4*>(bSrc + (size_t)8 * NHW);
        #pragma unroll
        for (int j = 0; j < 4; j++) {
            uint32_t off = am*16 + ((j ^ hA) << 2) + ah*2;
            *reinterpret_cast<uint2*>(&As[0][off]) =
                make_uint2(__float_as_uint((&fa0.x)[j]), __float_as_uint((&fa1.x)[j]));
            uint32_t v0 = CVTB ? f2tf32((&fb0.x)[j]) : __float_as_uint((&fb0.x)[j]);
            uint32_t v1 = CVTB ? f2tf32((&fb1.x)[j]) : __float_as_uint((&fb1.x)[j]);
            Bs[0][bk0][bcol[j]]     = v0;
            Bs[0][bk0 + 8][bcol[j]] = v1;
        }
    }
    __syncthreads();

    int buf = 0;
    for (int kc = 0; kc < 16; kc++) {
        const bool has_next = (kc + 1) < 16;
        float4 fa0, fa1, fb0, fb1;
        if (has_next) {
            const int kn = (kc + 1) * 16;
            fa0 = *reinterpret_cast<const float4*>(aSrc + kn);
            fa1 = *reinterpret_cast<const float4*>(aSrc + kn + 4);
            fb0 = *reinterpret_cast<const float4*>(bSrc + (size_t)kn * NHW);
            fb1 = *reinterpret_cast<const float4*>(bSrc + (size_t)(kn + 8) * NHW);
        }

        uint4 aq[2][2];
        #pragma unroll
        for (int mt = 0; mt < 2; mt++)
            #pragma unroll
            for (int mh = 0; mh < 2; mh++) {
                int m = wm*32 + mt*16 + mh*8 + gID;
                uint32_t off = m*16 + (((qid ^ ((m ^ (m >> 2)) & 3))) << 2);
                aq[mt][mh] = *reinterpret_cast<const uint4*>(&As[buf][off]);
            }

        #pragma unroll
        for (int ks = 0; ks < 2; ks++) {
            uint4 bq[2][2];
            #pragma unroll
            for (int kh = 0; kh < 2; kh++)
                #pragma unroll
                for (int bl = 0; bl < 2; bl++) {
                    int krow = ks*8 + kh*4 + qid;
                    int ncol = (wn*2 + bl)*32 + gID*4;
                    bq[kh][bl] = *reinterpret_cast<const uint4*>(&Bs[buf][krow][ncol]);
                }

            #pragma unroll
            for (int mt = 0; mt < 2; mt++) {
                uint32_t a[4];
                if (ks == 0) {
                    a[0] = aq[mt][0].x; a[1] = aq[mt][1].x;
                    a[2] = aq[mt][0].y; a[3] = aq[mt][1].y;
                } else {
                    a[0] = aq[mt][0].z; a[1] = aq[mt][1].z;
                    a[2] = aq[mt][0].w; a[3] = aq[mt][1].w;
                }
                #pragma unroll
                for (int bl = 0; bl < 2; bl++) {
                    #pragma unroll
                    for (int c = 0; c < 4; c++) {
                        uint32_t b[2];
                        b[0] = (&bq[0][bl].x)[c];
                        b[1] = (&bq[1][bl].x)[c];
                        mma_tf32(acc[mt][bl*4 + c], a, b);
                    }
                }
            }
        }

        if (has_next) {
            const int nb_ = buf ^ 1;
            #pragma unroll
            for (int j = 0; j < 4; j++) {
                uint32_t off = am*16 + ((j ^ hA) << 2) + ah*2;
                *reinterpret_cast<uint2*>(&As[nb_][off]) =
                    make_uint2(__float_as_uint((&fa0.x)[j]), __float_as_uint((&fa1.x)[j]));
                uint32_t v0 = CVTB ? f2tf32((&fb0.x)[j]) : __float_as_uint((&fb0.x)[j]);
                uint32_t v1 = CVTB ? f2tf32((&fb1.x)[j]) : __float_as_uint((&fb1.x)[j]);
                Bs[nb_][bk0][bcol[j]]     = v0;
                Bs[nb_][bk0 + 8][bcol[j]] = v1;
            }
            __syncthreads();
            buf = nb_;
        }
    }

    #pragma unroll
    for (int mt = 0; mt < 2; mt++) {
        #pragma unroll
        for (int half = 0; half < 2; half++) {
            const int o = m0 + wm*32 + mt*16 + half*8 + gID;
            float sc = 0.f, mm = 0.f, bb;
            if (BN_GELU) {
                sc = p0[o] * rsqrtf(p3[o] + EPSV);
                mm = p2[o];
                bb = p1[o];
            } else {
                bb = p0[o];
            }
            float* cp = Cm + (size_t)o * NHW + n0 + wn*64 + qid*2;
            #pragma unroll
            for (int nt = 0; nt < 8; nt++) {
                float z0 = acc[mt][nt][half*2 + 0];
                float z1 = acc[mt][nt][half*2 + 1];
                if (BN_GELU) {
                    z0 = (z0 - mm) * sc + bb; z0 = f2tf32f(gelu_exact(z0));
                    z1 = (z1 - mm) * sc + bb; z1 = f2tf32f(gelu_exact(z1));
                } else {
                    z0 += bb; z1 += bb;
                }
                *reinterpret_cast<float2*>(cp + nt*8) = make_float2(z0, z1);
            }
        }
    }
}

// 3b) Expert-2 feature stage: feat = bn_gelu(e2_k @ x[b]) — only for idx==2
__global__ void __launch_bounds__(256, 2) feat_gemm_kernel(
    const float* __restrict__ x,
    const float* __restrict__ g, const float* __restrict__ bt,
    const float* __restrict__ m, const float* __restrict__ v)
{
    int b = blockIdx.z;
    if (g_idx[b] != 2) return;
    mma_gemm_tile<true, true>(g_wt[3], x + (size_t)b*NCHW, g_feat + (size_t)b*NCHW, g, bt, m, v);
}

// 4) Final pointwise: out[b] = e{idx}_pw @ feat[b] + e{idx}_pb
__global__ void __launch_bounds__(256, 2) out_gemm_kernel(
    const float* __restrict__ pb0, const float* __restrict__ pb1,
    const float* __restrict__ pb2, float* __restrict__ out)
{
    int b = blockIdx.z;
    int e = g_idx[b];
    const float* pb = (e == 0) ? pb0 : (e == 1 ? pb1 : pb2);
    mma_gemm_tile<false, false>(g_wt[e], g_feat + (size_t)b*NCHW, out + (size_t)b*NCHW,
                                pb, nullptr, nullptr, nullptr);
}

// ---------------------------------------------------------------------------
extern "C" void kernel_launch(void* const* d_in, const int* in_sizes, int n_in,
                              void* d_out, int out_size) {
    const float* x    = (const float*)d_in[0];
    const float* rw   = (const float*)d_in[1];
    const float* rb   = (const float*)d_in[2];
    const float* e0_k = (const float*)d_in[3];
    const float* e0_g = (const float*)d_in[4];
    const float* e0_b = (const float*)d_in[5];
    const float* e0_m = (const float*)d_in[6];
    const float* e0_v = (const float*)d_in[7];
    const float* e0_pw= (const float*)d_in[8];
    const float* e0_pb= (const float*)d_in[9];
    const float* e1_k = (const float*)d_in[10];
    const float* e1_g = (const float*)d_in[11];
    const float* e1_b = (const float*)d_in[12];
    const float* e1_m = (const float*)d_in[13];
    const float* e1_v = (const float*)d_in[14];
    const float* e1_pw= (const float*)d_in[15];
    const float* e1_pb= (const float*)d_in[16];
    const float* e2_k = (const float*)d_in[17];
    const float* e2_g = (const float*)d_in[18];
    const float* e2_b = (const float*)d_in[19];
    const float* e2_m = (const float*)d_in[20];
    const float* e2_v = (const float*)d_in[21];
    const float* e2_pw= (const float*)d_in[22];
    const float* e2_pb= (const float*)d_in[23];
    float* out = (float*)d_out;

    pool_kernel<<<NB*NC, 256>>>(x);
    prep_weights<<<1024, 256>>>(e0_pw, e1_pw, e2_pw, e2_k);
    route_kernel<<<1, 32>>>(rw, rb);

    dwconv_bn_gelu_kernel<<<dim3(NC, NB), 256>>>(
        x, e0_k, e0_g, e0_b, e0_m, e0_v,
           e1_k, e1_g, e1_b, e1_m, e1_v);

    dim3 ggrid(NHW/128, NC/128, NB);   // (32, 2, 32)
    feat_gemm_kernel<<<ggrid, 256>>>(x, e2_g, e2_b, e2_m, e2_v);
    out_gemm_kernel<<<ggrid, 256>>>(e0_pb, e1_pb, e2_pb, out);
}